// round 5
// baseline (speedup 1.0000x reference)
#include <cuda_runtime.h>
#include <math.h>
#include <stdint.h>

constexpr int B_ = 8;
constexpr int N_ = 1024;
constexpr int D_ = 256;
constexpr int K3D = 3 * D_;   // 768
constexpr int K3N = 3 * N_;   // 3072

// ---------------- scratch ----------------
__device__ float g_x3[(size_t)B_ * N_ * K3D];       // x expanded (A-pattern)
__device__ float g_U3[D_ * K3D];                    // U rows (B-pattern)
__device__ float g_U12T3[2 * D_ * K3D];             // scaled U (B-pattern)
__device__ float g_t3[(size_t)B_ * N_ * K3D];       // t expanded (A-pattern)
__device__ float g_xs3[(size_t)B_ * N_ * 2 * K3D];  // xs expanded (A-pattern), per-branch
__device__ float g_y3[(size_t)B_ * N_ * K3D];       // y expanded (B-pattern)
__device__ float g_yT3[(size_t)B_ * D_ * K3N];      // y^T expanded (B-pattern)
__device__ float g_scores[(size_t)B_ * 2 * N_ * N_];
__device__ float g_attn3[(size_t)B_ * N_ * K3N];    // selected attn expanded (A-pattern)
__device__ float g_pos[(size_t)N_ * N_];

// ---------------- helpers ----------------
__device__ __forceinline__ uint32_t smaddr(const void* p) {
    return (uint32_t)__cvta_generic_to_shared(p);
}
__device__ __forceinline__ void ldm_x4(uint32_t* r, uint32_t addr) {
    asm volatile("ldmatrix.sync.aligned.m8n8.x4.shared.b16 {%0,%1,%2,%3}, [%4];"
                 : "=r"(r[0]), "=r"(r[1]), "=r"(r[2]), "=r"(r[3]) : "r"(addr));
}
__device__ __forceinline__ void mma_tf32(float* c, const uint32_t* a, const uint32_t* b) {
    asm volatile("mma.sync.aligned.m16n8k8.row.col.f32.tf32.tf32.f32 "
                 "{%0,%1,%2,%3}, {%4,%5,%6,%7}, {%8,%9}, {%0,%1,%2,%3};"
                 : "+f"(c[0]), "+f"(c[1]), "+f"(c[2]), "+f"(c[3])
                 : "r"(a[0]), "r"(a[1]), "r"(a[2]), "r"(a[3]), "r"(b[0]), "r"(b[1]));
}
__device__ __forceinline__ uint32_t f2tf32(float x) {
    uint32_t u; asm("cvt.rna.tf32.f32 %0, %1;" : "=r"(u) : "f"(x)); return u;
}
__device__ __forceinline__ void cpa16(uint32_t dst, const float* src) {
    asm volatile("cp.async.cg.shared.global [%0], [%1], 16;" :: "r"(dst), "l"(src));
}
__device__ __forceinline__ void cp_commit() {
    asm volatile("cp.async.commit_group;" ::: "memory");
}
__device__ __forceinline__ void cp_wait2() {
    asm volatile("cp.async.wait_group 2;" ::: "memory");
}

__device__ __forceinline__ float blk_max(float v, volatile float* sm) {
    #pragma unroll
    for (int o = 16; o > 0; o >>= 1) v = fmaxf(v, __shfl_xor_sync(0xffffffffu, v, o));
    if ((threadIdx.x & 31) == 0) sm[threadIdx.x >> 5] = v;
    __syncthreads();
    float r = sm[0];
    #pragma unroll
    for (int i = 1; i < 8; i++) r = fmaxf(r, sm[i]);
    __syncthreads();
    return r;
}
__device__ __forceinline__ float blk_sum(float v, volatile float* sm) {
    #pragma unroll
    for (int o = 16; o > 0; o >>= 1) v += __shfl_xor_sync(0xffffffffu, v, o);
    if ((threadIdx.x & 31) == 0) sm[threadIdx.x >> 5] = v;
    __syncthreads();
    float r = sm[0];
    #pragma unroll
    for (int i = 1; i < 8; i++) r += sm[i];
    __syncthreads();
    return r;
}

// ---------------- pipelined NT GEMM on pre-expanded tf32 operands -----------
// C[m,n] = alpha * sum_k A[m,k]*Bm[n,k], K3 = 3K expanded.
// Block 128xBN, BK=16, 256 threads, 4-stage cp.async, XOR-swizzled smem.
// EPI: 0 = plain store; 1 = A-pattern expanded store (hi, lo, hi at +0/+256/+512
//      within 768-col segment selected by (c>>8)).
template <int BN, int EPI>
__device__ __forceinline__ void gemm3(
    const float* __restrict__ A, int lda,
    const float* __restrict__ Bm, int ldb,
    float* __restrict__ C, int ldc,
    int K3, float alpha)
{
    constexpr int BM = 128, BK = 16, NS = 4;
    constexpr int AST = BM * 64;         // bytes per A stage (row = 16 floats = 64B)
    constexpr int BST = BN * 64;
    constexpr int STG = AST + BST;
    constexpr int WN = BN / 2, nP = BN / 32;

    extern __shared__ float smem[];
    const uint32_t sbase = smaddr(smem);

    const int tid = threadIdx.x, lane = tid & 31, warp = tid >> 5;
    const int wm = (warp & 3) * 32, wn = (warp >> 2) * WN;
    const int m0 = blockIdx.y * BM, n0 = blockIdx.x * BN;

    // ---- cp.async producer mapping (chunk = 16B = 4 floats; 4 chunks/row) ----
    const int ar = tid >> 1;
    const int ac0 = (tid & 1) * 2;
    const float* aSrc = A + (size_t)(m0 + ar) * lda + ac0 * 4;
    const int asw_st = (ar >> 1) & 3;
    const uint32_t aD0 = sbase + ar * 64 + ((ac0 ^ asw_st) * 16);
    const uint32_t aD1 = sbase + ar * 64 + (((ac0 + 1) ^ asw_st) * 16);

    const int br = (BN == 128) ? (tid >> 1) : (tid >> 2);
    const int bc0 = (BN == 128) ? ((tid & 1) * 2) : (tid & 3);
    const float* bSrc = Bm + (size_t)(n0 + br) * ldb + bc0 * 4;
    const int bsw_st = (br >> 1) & 3;
    const uint32_t bD0 = sbase + AST + br * 64 + ((bc0 ^ bsw_st) * 16);
    const uint32_t bD1 = sbase + AST + br * 64 + (((bc0 + 1) ^ bsw_st) * 16);

    auto issue = [&](int kt, int slot) {
        const uint32_t so = (uint32_t)slot * STG;
        const int ko = kt * BK;
        cpa16(aD0 + so, aSrc + ko);
        cpa16(aD1 + so, aSrc + ko + 4);
        cpa16(bD0 + so, bSrc + ko);
        if (BN == 128) cpa16(bD1 + so, bSrc + ko + 4);
    };

    // ---- ldmatrix consumer per-lane addressing ----
    const int mat = lane >> 3, idx = lane & 7;
    const int arow = wm + (mat & 1) * 8 + idx;
    const int asw = (arow >> 1) & 3;
    const int ach = mat >> 1;
    const uint32_t aK0 = (uint32_t)((ach ^ asw) * 16);
    const uint32_t aK1 = (uint32_t)(((ach + 2) ^ asw) * 16);
    const uint32_t aBase = sbase + arow * 64;

    const int brow = wn + (mat >> 1) * 8 + idx;
    const int bsw = (brow >> 1) & 3;
    const int bch = mat & 1;
    const uint32_t bK0 = (uint32_t)((bch ^ bsw) * 16);
    const uint32_t bK1 = (uint32_t)(((bch + 2) ^ bsw) * 16);
    const uint32_t bBase = sbase + AST + brow * 64;

    float acc[2][2 * nP][4] = {};

    const int ktiles = K3 / BK;
    #pragma unroll
    for (int s = 0; s < NS - 1; s++) { issue(s, s); cp_commit(); }

    for (int kt = 0; kt < ktiles; kt++) {
        cp_wait2();
        __syncthreads();
        const uint32_t so = (uint32_t)(kt & 3) * STG;

        if (kt + NS - 1 < ktiles) issue(kt + NS - 1, (kt + NS - 1) & 3);
        cp_commit();

        #pragma unroll
        for (int k8 = 0; k8 < 2; k8++) {
            const uint32_t akk = k8 ? aK1 : aK0;
            const uint32_t bkk = k8 ? bK1 : bK0;
            uint32_t a0[4], a1[4];
            ldm_x4(a0, aBase + so + akk);
            ldm_x4(a1, aBase + so + akk + 16 * 64);
            #pragma unroll
            for (int p = 0; p < nP; p++) {
                uint32_t bf[4];
                ldm_x4(bf, bBase + so + bkk + p * 16 * 64);
                mma_tf32(acc[0][2 * p],     a0, bf);
                mma_tf32(acc[0][2 * p + 1], a0, bf + 2);
                mma_tf32(acc[1][2 * p],     a1, bf);
                mma_tf32(acc[1][2 * p + 1], a1, bf + 2);
            }
        }
    }

    // ---- epilogue ----
    const int g = lane >> 2, tig = lane & 3;
    #pragma unroll
    for (int f = 0; f < 2; f++) {
        #pragma unroll
        for (int q = 0; q < 2 * nP; q++) {
            const int r = m0 + wm + f * 16 + g;
            const int c = n0 + wn + q * 8 + tig * 2;
            #pragma unroll
            for (int h = 0; h < 2; h++) {
                const int rr = r + h * 8;
                float v0 = alpha * acc[f][q][2 * h];
                float v1 = alpha * acc[f][q][2 * h + 1];
                if (EPI == 0) {
                    *(float2*)(C + (size_t)rr * ldc + c) = make_float2(v0, v1);
                } else {
                    // expanded A-pattern: [hi | lo | hi] within 768-col segment
                    const int seg = c >> 8, j2 = c & 255;
                    float* dst = C + (size_t)rr * ldc + seg * 768 + j2;
                    float h0 = __uint_as_float(f2tf32(v0));
                    float h1 = __uint_as_float(f2tf32(v1));
                    float l0 = __uint_as_float(f2tf32(v0 - h0));
                    float l1 = __uint_as_float(f2tf32(v1 - h1));
                    *(float2*)(dst)       = make_float2(h0, h1);
                    *(float2*)(dst + 256) = make_float2(l0, l1);
                    *(float2*)(dst + 512) = make_float2(h0, h1);
                }
            }
        }
    }
}

// smem bytes
constexpr int SM3_128 = 4 * (128 + 128) * 64;  // 65536
constexpr int SM3_64  = 4 * (128 + 64) * 64;   // 49152

// ---------------- GEMM wrappers ----------------
__global__ void __launch_bounds__(256, 2) k_g_t() {
    gemm3<64, 1>(g_x3, K3D, g_U3, K3D, g_t3, K3D, K3D, 1.0f);
}
__global__ void __launch_bounds__(256, 2) k_g_xs() {
    gemm3<128, 1>(g_t3, K3D, g_U12T3, K3D, g_xs3, 2 * K3D, K3D, 1.0f);
}
__global__ void __launch_bounds__(256, 2) k_g_sc() {
    int z = blockIdx.z;
    int b = z >> 1, k = z & 1;
    gemm3<128, 0>(g_xs3 + (size_t)b * N_ * (2 * K3D) + k * K3D, 2 * K3D,
                  g_y3 + (size_t)b * N_ * K3D, K3D,
                  g_scores + (size_t)z * N_ * N_, N_,
                  K3D, 0.0625f);
}
__global__ void __launch_bounds__(256, 2) k_g_out(float* __restrict__ out) {
    int b = blockIdx.z;
    gemm3<64, 0>(g_attn3 + (size_t)b * N_ * K3N, K3N,
                 g_yT3 + (size_t)b * D_ * K3N, K3N,
                 out + (size_t)b * N_ * D_, D_,
                 K3N, 1.0f);
}

// ---------------- expansion / prep kernels ----------------
__device__ __forceinline__ void hilo(float v, float& h, float& l) {
    h = __uint_as_float(f2tf32(v));
    l = __uint_as_float(f2tf32(v - h));
}

// x -> A-pattern [hi, lo, hi]
__global__ void k_x3(const float* __restrict__ x) {
    int i = blockIdx.x * 256 + threadIdx.x;  // B*N*D
    int r = i >> 8, d = i & 255;
    float h, l; hilo(x[i], h, l);
    float* dst = g_x3 + (size_t)r * K3D;
    dst[d] = h; dst[256 + d] = l; dst[512 + d] = h;
}
// U rows -> B-pattern [hi, hi, lo]
__global__ void k_U3p(const float* __restrict__ U) {
    int i = blockIdx.x * 256 + threadIdx.x;  // D*D, i = j*256+d
    int j = i >> 8, d = i & 255;
    float h, l; hilo(U[i], h, l);
    float* dst = g_U3 + (size_t)j * K3D;
    dst[d] = h; dst[256 + d] = h; dst[512 + d] = l;
}
// U12T -> B-pattern
__global__ void k_U12T3p(const float* __restrict__ U,
                         const float* __restrict__ S1,
                         const float* __restrict__ S2) {
    int i = blockIdx.x * 256 + threadIdx.x;  // 512*256
    int r = i >> 8, d = i & 255;
    int k = r >> 8, j = r & 255;
    float v = fabsf(k ? S2[d] : S1[d]) * U[d * 256 + j];
    float h, l; hilo(v, h, l);
    float* dst = g_U12T3 + (size_t)r * K3D;
    dst[d] = h; dst[256 + d] = h; dst[512 + d] = l;
}
// y -> B-pattern
__global__ void k_y3p(const float* __restrict__ y) {
    int i = blockIdx.x * 256 + threadIdx.x;  // B*N*D
    int r = i >> 8, d = i & 255;
    float h, l; hilo(y[i], h, l);
    float* dst = g_y3 + (size_t)r * K3D;
    dst[d] = h; dst[256 + d] = h; dst[512 + d] = l;
}
// y^T -> B-pattern over k=m (K3N)
__global__ void k_yT3p(const float* __restrict__ y) {
    __shared__ float tile[32][33];
    int b = blockIdx.z;
    int m0 = blockIdx.y * 32, j0 = blockIdx.x * 32;
    int tx = threadIdx.x, ty = threadIdx.y;
    #pragma unroll
    for (int i = ty; i < 32; i += 8)
        tile[i][tx] = y[((size_t)b * N_ + m0 + i) * D_ + j0 + tx];
    __syncthreads();
    #pragma unroll
    for (int i = ty; i < 32; i += 8) {
        float h, l; hilo(tile[tx][i], h, l);
        size_t base = ((size_t)b * D_ + j0 + i) * K3N + m0 + tx;
        g_yT3[base] = h; g_yT3[base + 1024] = h; g_yT3[base + 2048] = l;
    }
}

// pos softmax
__global__ void k_pos(const float* __restrict__ coords,
                      const float* __restrict__ pos_emb,
                      const float* __restrict__ p_temp) {
    __shared__ float pe[6];
    __shared__ float sm[8];
    int n = blockIdx.x;
    int t = threadIdx.x;
    if (t < 6) pe[t] = pos_emb[n * 6 + t];
    __syncthreads();
    float pt = -fabsf(p_temp[0]);
    float lg[4];
    float lmax = -1e30f;
    #pragma unroll
    for (int i = 0; i < 4; i++) {
        int m = i * 256 + t;
        const float* c = coords + ((size_t)n * N_ + m) * 6;
        float a = c[0] * pe[0] + c[1] * pe[1] + c[2] * pe[2]
                + c[3] * pe[3] + c[4] * pe[4] + c[5] * pe[5];
        lg[i] = pt * a;
        lmax = fmaxf(lmax, lg[i]);
    }
    float mx = blk_max(lmax, sm);
    float lsum = 0.f;
    #pragma unroll
    for (int i = 0; i < 4; i++) { lg[i] = __expf(lg[i] - mx); lsum += lg[i]; }
    float s = blk_sum(lsum, sm);
    float inv = 1.0f / s;
    #pragma unroll
    for (int i = 0; i < 4; i++)
        g_pos[(size_t)n * N_ + i * 256 + t] = lg[i] * inv;
}

// softmax/blend/entropy/route; writes selected attn row expanded (A-pattern)
__global__ void k_mix(const float* __restrict__ gating,
                      const float* __restrict__ h_temp,
                      float* __restrict__ heat) {
    __shared__ float sm[8];
    int bn = blockIdx.x;
    int b = bn >> 10;
    int n = bn & (N_ - 1);
    int t = threadIdx.x;

    size_t base0 = ((size_t)(b * 2 + 0) * N_ + n) * N_;
    size_t base1 = ((size_t)(b * 2 + 1) * N_ + n) * N_;

    float s0[4], s1[4], pp[4];
    float lm0 = -1e30f, lm1 = -1e30f;
    #pragma unroll
    for (int i = 0; i < 4; i++) {
        int m = i * 256 + t;
        s0[i] = g_scores[base0 + m];
        s1[i] = g_scores[base1 + m];
        pp[i] = g_pos[(size_t)n * N_ + m];
        lm0 = fmaxf(lm0, s0[i]);
        lm1 = fmaxf(lm1, s1[i]);
    }
    float mx0 = blk_max(lm0, sm);
    float mx1 = blk_max(lm1, sm);

    float ls0 = 0.f, ls1 = 0.f;
    #pragma unroll
    for (int i = 0; i < 4; i++) {
        s0[i] = __expf(s0[i] - mx0); ls0 += s0[i];
        s1[i] = __expf(s1[i] - mx1); ls1 += s1[i];
    }
    float sum0 = blk_sum(ls0, sm);
    float sum1 = blk_sum(ls1, sm);
    float inv0 = 1.0f / sum0, inv1 = 1.0f / sum1;

    float g = 1.0f / (1.0f + __expf(-gating[0]));
    float og = 1.0f - g;

    float p0[4], p1[4];
    float le0 = 0.f, le1 = 0.f;
    #pragma unroll
    for (int i = 0; i < 4; i++) {
        p0[i] = og * s0[i] * inv0 + g * pp[i];
        p1[i] = og * s1[i] * inv1 + g * pp[i];
        le0 -= p0[i] * __logf(p0[i] + 1e-8f);
        le1 -= p1[i] * __logf(p1[i] + 1e-8f);
    }
    float ent0 = blk_sum(le0, sm);
    float ent1 = blk_sum(le1, sm);

    float ht = h_temp[0];
    float hm0 = 2.0f - 2.0f / (1.0f + __expf(-ht * ent0));
    float hm1 = 2.0f - 2.0f / (1.0f + __expf(-ht * ent1));
    int sel = (hm0 >= hm1) ? 0 : 1;

    #pragma unroll
    for (int i = 0; i < 4; i++) {
        float v = sel ? p1[i] : p0[i];
        float h, l; hilo(v, h, l);
        size_t base = (size_t)bn * K3N + i * 256 + t;
        g_attn3[base] = h;
        g_attn3[base + 1024] = l;
        g_attn3[base + 2048] = h;
    }

    if (t == 0) heat[bn] = sel ? hm1 : hm0;
}

// ---------------- launch ----------------
extern "C" void kernel_launch(void* const* d_in, const int* in_sizes, int n_in,
                              void* d_out, int out_size) {
    const float* x       = (const float*)d_in[0];
    const float* y       = (const float*)d_in[1];
    const float* coords  = (const float*)d_in[2];
    const float* U       = (const float*)d_in[3];
    const float* S1      = (const float*)d_in[4];
    const float* S2      = (const float*)d_in[5];
    const float* gating  = (const float*)d_in[6];
    const float* h_temp  = (const float*)d_in[7];
    const float* p_temp  = (const float*)d_in[8];
    const float* pos_emb = (const float*)d_in[9];

    float* out  = (float*)d_out;
    float* heat = out + (size_t)B_ * N_ * D_;

    cudaFuncSetAttribute(k_g_t,   cudaFuncAttributeMaxDynamicSharedMemorySize, SM3_64);
    cudaFuncSetAttribute(k_g_xs,  cudaFuncAttributeMaxDynamicSharedMemorySize, SM3_128);
    cudaFuncSetAttribute(k_g_sc,  cudaFuncAttributeMaxDynamicSharedMemorySize, SM3_128);
    cudaFuncSetAttribute(k_g_out, cudaFuncAttributeMaxDynamicSharedMemorySize, SM3_64);

    // prep / expansion
    k_x3<<<(B_ * N_ * D_) / 256, 256>>>(x);
    k_U3p<<<(D_ * D_) / 256, 256>>>(U);
    k_U12T3p<<<(2 * D_ * D_) / 256, 256>>>(U, S1, S2);
    k_y3p<<<(B_ * N_ * D_) / 256, 256>>>(y);
    k_yT3p<<<dim3(D_ / 32, N_ / 32, B_), dim3(32, 8)>>>(y);
    k_pos<<<N_, 256>>>(coords, pos_emb, p_temp);

    // GEMM chain
    k_g_t<<<dim3(D_ / 64, (B_ * N_) / 128), 256, SM3_64>>>();
    k_g_xs<<<dim3((2 * D_) / 128, (B_ * N_) / 128), 256, SM3_128>>>();
    k_g_sc<<<dim3(N_ / 128, N_ / 128, B_ * 2), 256, SM3_128>>>();

    k_mix<<<B_ * N_, 256>>>(gating, h_temp, heat);

    k_g_out<<<dim3(D_ / 64, N_ / 128, B_), 256, SM3_64>>>(out);
}

// round 6
// speedup vs baseline: 1.1444x; 1.1444x over previous
#include <cuda_runtime.h>
#include <math.h>
#include <stdint.h>

constexpr int B_ = 8;
constexpr int N_ = 1024;
constexpr int D_ = 256;

// ---------------- scratch ----------------
__device__ float g_t[(size_t)B_ * N_ * D_];
__device__ float g_xs[(size_t)B_ * N_ * 2 * D_];
__device__ float g_U12T[2 * D_ * D_];
__device__ float g_pos[(size_t)N_ * N_];
__device__ float g_scores[(size_t)B_ * 2 * N_ * N_];
__device__ float g_attn[(size_t)B_ * N_ * N_];
__device__ float g_yT[(size_t)B_ * D_ * N_];

// ---------------- helpers ----------------
__device__ __forceinline__ uint32_t smaddr(const void* p) {
    return (uint32_t)__cvta_generic_to_shared(p);
}
__device__ __forceinline__ void ldm_x4(uint32_t* r, uint32_t addr) {
    asm volatile("ldmatrix.sync.aligned.m8n8.x4.shared.b16 {%0,%1,%2,%3}, [%4];"
                 : "=r"(r[0]), "=r"(r[1]), "=r"(r[2]), "=r"(r[3]) : "r"(addr));
}
__device__ __forceinline__ void mma_tf32(float* c, const uint32_t* a, const uint32_t* b) {
    asm volatile("mma.sync.aligned.m16n8k8.row.col.f32.tf32.tf32.f32 "
                 "{%0,%1,%2,%3}, {%4,%5,%6,%7}, {%8,%9}, {%0,%1,%2,%3};"
                 : "+f"(c[0]), "+f"(c[1]), "+f"(c[2]), "+f"(c[3])
                 : "r"(a[0]), "r"(a[1]), "r"(a[2]), "r"(a[3]), "r"(b[0]), "r"(b[1]));
}
__device__ __forceinline__ uint32_t f2tf32(float x) {
    uint32_t u; asm("cvt.rna.tf32.f32 %0, %1;" : "=r"(u) : "f"(x)); return u;
}
// split a 4-reg raw fp32 fragment into tf32 hi/lo fragments
__device__ __forceinline__ void cvt4(const uint32_t* raw, uint32_t* h, uint32_t* l) {
    #pragma unroll
    for (int i = 0; i < 4; i++) {
        float v = __uint_as_float(raw[i]);
        uint32_t hh = f2tf32(v);
        h[i] = hh;
        l[i] = f2tf32(v - __uint_as_float(hh));
    }
}
__device__ __forceinline__ void cpa16(uint32_t dst, const float* src) {
    asm volatile("cp.async.cg.shared.global [%0], [%1], 16;" :: "r"(dst), "l"(src));
}
__device__ __forceinline__ void cp_commit() {
    asm volatile("cp.async.commit_group;" ::: "memory");
}
__device__ __forceinline__ void cp_wait2() {
    asm volatile("cp.async.wait_group 2;" ::: "memory");
}

__device__ __forceinline__ float blk_max(float v, volatile float* sm) {
    #pragma unroll
    for (int o = 16; o > 0; o >>= 1) v = fmaxf(v, __shfl_xor_sync(0xffffffffu, v, o));
    if ((threadIdx.x & 31) == 0) sm[threadIdx.x >> 5] = v;
    __syncthreads();
    float r = sm[0];
    #pragma unroll
    for (int i = 1; i < 8; i++) r = fmaxf(r, sm[i]);
    __syncthreads();
    return r;
}
__device__ __forceinline__ float blk_sum(float v, volatile float* sm) {
    #pragma unroll
    for (int o = 16; o > 0; o >>= 1) v += __shfl_xor_sync(0xffffffffu, v, o);
    if ((threadIdx.x & 31) == 0) sm[threadIdx.x >> 5] = v;
    __syncthreads();
    float r = sm[0];
    #pragma unroll
    for (int i = 1; i < 8; i++) r += sm[i];
    __syncthreads();
    return r;
}

// ---------------- NT GEMM, raw-fp32 smem + register-side 3xTF32 split --------
// C[m,n] = alpha * sum_k A[m,k]*Bm[n,k]. Block 128xBN, BK=16, 256 threads,
// 4-stage cp.async pipeline, XOR-swizzled 64B-row smem tiles.
template <int BN>
__device__ __forceinline__ void gemm_rs(
    const float* __restrict__ A, int lda,
    const float* __restrict__ Bm, int ldb,
    float* __restrict__ C, int ldc,
    int K, float alpha)
{
    constexpr int BM = 128, BK = 16, NS = 4;
    constexpr int AST = BM * 64;   // bytes per A stage (row = 16 floats = 64B)
    constexpr int BST = BN * 64;
    constexpr int STG = AST + BST;
    constexpr int WN = BN / 2, nP = BN / 32;

    extern __shared__ float smem[];
    const uint32_t sbase = smaddr(smem);

    const int tid = threadIdx.x, lane = tid & 31, warp = tid >> 5;
    const int wm = (warp & 3) * 32, wn = (warp >> 2) * WN;
    const int m0 = blockIdx.y * BM, n0 = blockIdx.x * BN;

    // ---- cp.async producer mapping (16B chunks, 4 chunks per 64B row) ----
    const int ar = tid >> 1;
    const int ac0 = (tid & 1) * 2;
    const float* aSrc = A + (size_t)(m0 + ar) * lda + ac0 * 4;
    const int asw_st = (ar >> 1) & 3;
    const uint32_t aD0 = sbase + ar * 64 + ((ac0 ^ asw_st) * 16);
    const uint32_t aD1 = sbase + ar * 64 + (((ac0 + 1) ^ asw_st) * 16);

    const int br = (BN == 128) ? (tid >> 1) : (tid >> 2);
    const int bc0 = (BN == 128) ? ((tid & 1) * 2) : (tid & 3);
    const float* bSrc = Bm + (size_t)(n0 + br) * ldb + bc0 * 4;
    const int bsw_st = (br >> 1) & 3;
    const uint32_t bD0 = sbase + AST + br * 64 + ((bc0 ^ bsw_st) * 16);
    const uint32_t bD1 = sbase + AST + br * 64 + (((bc0 + 1) ^ bsw_st) * 16);

    auto issue = [&](int kt, int slot) {
        const uint32_t so = (uint32_t)slot * STG;
        const int ko = kt * BK;
        cpa16(aD0 + so, aSrc + ko);
        cpa16(aD1 + so, aSrc + ko + 4);
        cpa16(bD0 + so, bSrc + ko);
        if (BN == 128) cpa16(bD1 + so, bSrc + ko + 4);
    };

    // ---- ldmatrix consumer addressing ----
    const int mat = lane >> 3, idx = lane & 7;
    const int arow = wm + (mat & 1) * 8 + idx;
    const int asw = (arow >> 1) & 3;
    const int ach = mat >> 1;
    const uint32_t aK0 = (uint32_t)((ach ^ asw) * 16);
    const uint32_t aK1 = (uint32_t)(((ach + 2) ^ asw) * 16);
    const uint32_t aBase = sbase + arow * 64;

    const int brow = wn + (mat >> 1) * 8 + idx;
    const int bsw = (brow >> 1) & 3;
    const int bch = mat & 1;
    const uint32_t bK0 = (uint32_t)((bch ^ bsw) * 16);
    const uint32_t bK1 = (uint32_t)(((bch + 2) ^ bsw) * 16);
    const uint32_t bBase = sbase + AST + brow * 64;

    float acc[2][2 * nP][4] = {};

    const int ktiles = K / BK;
    #pragma unroll
    for (int s = 0; s < NS - 1; s++) { issue(s, s); cp_commit(); }

    for (int kt = 0; kt < ktiles; kt++) {
        cp_wait2();
        __syncthreads();
        const uint32_t so = (uint32_t)(kt & 3) * STG;

        if (kt + NS - 1 < ktiles) issue(kt + NS - 1, (kt + NS - 1) & 3);
        cp_commit();

        #pragma unroll
        for (int k8 = 0; k8 < 2; k8++) {
            const uint32_t akk = k8 ? aK1 : aK0;
            const uint32_t bkk = k8 ? bK1 : bK0;
            uint32_t ar0[4], ar1[4];
            ldm_x4(ar0, aBase + so + akk);
            ldm_x4(ar1, aBase + so + akk + 16 * 64);
            uint32_t ah[2][4], al[2][4];
            cvt4(ar0, ah[0], al[0]);
            cvt4(ar1, ah[1], al[1]);
            #pragma unroll
            for (int p = 0; p < nP; p++) {
                uint32_t braw[4], bh[4], bl[4];
                ldm_x4(braw, bBase + so + bkk + p * 16 * 64);
                cvt4(braw, bh, bl);
                #pragma unroll
                for (int f = 0; f < 2; f++) {
                    mma_tf32(acc[f][2 * p],     ah[f], bh);
                    mma_tf32(acc[f][2 * p + 1], ah[f], bh + 2);
                    mma_tf32(acc[f][2 * p],     ah[f], bl);
                    mma_tf32(acc[f][2 * p + 1], ah[f], bl + 2);
                    mma_tf32(acc[f][2 * p],     al[f], bh);
                    mma_tf32(acc[f][2 * p + 1], al[f], bh + 2);
                }
            }
        }
    }

    // ---- epilogue ----
    const int g = lane >> 2, tig = lane & 3;
    #pragma unroll
    for (int f = 0; f < 2; f++) {
        #pragma unroll
        for (int q = 0; q < 2 * nP; q++) {
            const int r = m0 + wm + f * 16 + g;
            const int c = n0 + wn + q * 8 + tig * 2;
            float2 v0 = {alpha * acc[f][q][0], alpha * acc[f][q][1]};
            float2 v1 = {alpha * acc[f][q][2], alpha * acc[f][q][3]};
            *(float2*)(C + (size_t)r * ldc + c) = v0;
            *(float2*)(C + (size_t)(r + 8) * ldc + c) = v1;
        }
    }
}

// smem bytes (4 stages, raw fp32)
constexpr int SMA128 = 4 * (128 + 128) * 64;  // 65536
constexpr int SMA64  = 4 * (128 + 64) * 64;   // 49152

// ---------------- GEMM wrappers ----------------
__global__ void __launch_bounds__(256, 2)
k_gemm_t(const float* __restrict__ x, const float* __restrict__ U) {
    gemm_rs<64>(x, D_, U, D_, g_t, D_, D_, 1.0f);
}
__global__ void __launch_bounds__(256, 2)
k_gemm_xs() {
    gemm_rs<128>(g_t, D_, g_U12T, D_, g_xs, 2 * D_, D_, 1.0f);
}
__global__ void __launch_bounds__(256, 2)
k_gemm_scores(const float* __restrict__ y) {
    int z = blockIdx.z;
    int b = z >> 1, k = z & 1;
    gemm_rs<128>(g_xs + (size_t)b * N_ * (2 * D_) + k * D_, 2 * D_,
                 y + (size_t)b * N_ * D_, D_,
                 g_scores + (size_t)z * N_ * N_, N_,
                 D_, 0.0625f);
}
__global__ void __launch_bounds__(256, 2)
k_gemm_out(float* __restrict__ out) {
    int b = blockIdx.z;
    gemm_rs<64>(g_attn + (size_t)b * N_ * N_, N_,
                g_yT + (size_t)b * D_ * N_, N_,
                out + (size_t)b * N_ * D_, D_,
                N_, 1.0f);
}

// ---------------- prep kernels ----------------
__global__ void k_prep_u(const float* __restrict__ U,
                         const float* __restrict__ S1,
                         const float* __restrict__ S2) {
    int idxx = blockIdx.x * blockDim.x + threadIdx.x;
    int r = idxx >> 8;
    int d = idxx & 255;
    int k = r >> 8;
    int j = r & 255;
    float s = fabsf(k ? S2[d] : S1[d]);
    g_U12T[idxx] = s * U[d * 256 + j];
}

__global__ void k_transpose_y(const float* __restrict__ y) {
    __shared__ float tile[32][33];
    int b = blockIdx.z;
    int m0 = blockIdx.y * 32, j0 = blockIdx.x * 32;
    int tx = threadIdx.x, ty = threadIdx.y;
    #pragma unroll
    for (int i = ty; i < 32; i += 8)
        tile[i][tx] = y[((size_t)b * N_ + m0 + i) * D_ + j0 + tx];
    __syncthreads();
    #pragma unroll
    for (int i = ty; i < 32; i += 8)
        g_yT[((size_t)b * D_ + j0 + i) * N_ + m0 + tx] = tile[tx][i];
}

__global__ void k_pos(const float* __restrict__ coords,
                      const float* __restrict__ pos_emb,
                      const float* __restrict__ p_temp) {
    __shared__ float pe[6];
    __shared__ float sm[8];
    int n = blockIdx.x;
    int t = threadIdx.x;
    if (t < 6) pe[t] = pos_emb[n * 6 + t];
    __syncthreads();
    float pt = -fabsf(p_temp[0]);
    float lg[4];
    float lmax = -1e30f;
    #pragma unroll
    for (int i = 0; i < 4; i++) {
        int m = i * 256 + t;
        const float* c = coords + ((size_t)n * N_ + m) * 6;
        float a = c[0] * pe[0] + c[1] * pe[1] + c[2] * pe[2]
                + c[3] * pe[3] + c[4] * pe[4] + c[5] * pe[5];
        lg[i] = pt * a;
        lmax = fmaxf(lmax, lg[i]);
    }
    float mx = blk_max(lmax, sm);
    float lsum = 0.f;
    #pragma unroll
    for (int i = 0; i < 4; i++) { lg[i] = __expf(lg[i] - mx); lsum += lg[i]; }
    float s = blk_sum(lsum, sm);
    float inv = 1.0f / s;
    #pragma unroll
    for (int i = 0; i < 4; i++)
        g_pos[(size_t)n * N_ + i * 256 + t] = lg[i] * inv;
}

__global__ void k_mix(const float* __restrict__ gating,
                      const float* __restrict__ h_temp,
                      float* __restrict__ heat) {
    __shared__ float sm[8];
    int bn = blockIdx.x;
    int b = bn >> 10;
    int n = bn & (N_ - 1);
    int t = threadIdx.x;

    size_t base0 = ((size_t)(b * 2 + 0) * N_ + n) * N_;
    size_t base1 = ((size_t)(b * 2 + 1) * N_ + n) * N_;

    float s0[4], s1[4], pp[4];
    float lm0 = -1e30f, lm1 = -1e30f;
    #pragma unroll
    for (int i = 0; i < 4; i++) {
        int m = i * 256 + t;
        s0[i] = g_scores[base0 + m];
        s1[i] = g_scores[base1 + m];
        pp[i] = g_pos[(size_t)n * N_ + m];
        lm0 = fmaxf(lm0, s0[i]);
        lm1 = fmaxf(lm1, s1[i]);
    }
    float mx0 = blk_max(lm0, sm);
    float mx1 = blk_max(lm1, sm);

    float ls0 = 0.f, ls1 = 0.f;
    #pragma unroll
    for (int i = 0; i < 4; i++) {
        s0[i] = __expf(s0[i] - mx0); ls0 += s0[i];
        s1[i] = __expf(s1[i] - mx1); ls1 += s1[i];
    }
    float sum0 = blk_sum(ls0, sm);
    float sum1 = blk_sum(ls1, sm);
    float inv0 = 1.0f / sum0, inv1 = 1.0f / sum1;

    float g = 1.0f / (1.0f + __expf(-gating[0]));
    float og = 1.0f - g;

    float p0[4], p1[4];
    float le0 = 0.f, le1 = 0.f;
    #pragma unroll
    for (int i = 0; i < 4; i++) {
        p0[i] = og * s0[i] * inv0 + g * pp[i];
        p1[i] = og * s1[i] * inv1 + g * pp[i];
        le0 -= p0[i] * __logf(p0[i] + 1e-8f);
        le1 -= p1[i] * __logf(p1[i] + 1e-8f);
    }
    float ent0 = blk_sum(le0, sm);
    float ent1 = blk_sum(le1, sm);

    float ht = h_temp[0];
    float hm0 = 2.0f - 2.0f / (1.0f + __expf(-ht * ent0));
    float hm1 = 2.0f - 2.0f / (1.0f + __expf(-ht * ent1));
    int sel = (hm0 >= hm1) ? 0 : 1;

    #pragma unroll
    for (int i = 0; i < 4; i++)
        g_attn[(size_t)bn * N_ + i * 256 + t] = sel ? p1[i] : p0[i];

    if (t == 0) heat[bn] = sel ? hm1 : hm0;
}

// ---------------- launch ----------------
extern "C" void kernel_launch(void* const* d_in, const int* in_sizes, int n_in,
                              void* d_out, int out_size) {
    const float* x       = (const float*)d_in[0];
    const float* y       = (const float*)d_in[1];
    const float* coords  = (const float*)d_in[2];
    const float* U       = (const float*)d_in[3];
    const float* S1      = (const float*)d_in[4];
    const float* S2      = (const float*)d_in[5];
    const float* gating  = (const float*)d_in[6];
    const float* h_temp  = (const float*)d_in[7];
    const float* p_temp  = (const float*)d_in[8];
    const float* pos_emb = (const float*)d_in[9];

    float* out  = (float*)d_out;
    float* heat = out + (size_t)B_ * N_ * D_;

    cudaFuncSetAttribute(k_gemm_t,      cudaFuncAttributeMaxDynamicSharedMemorySize, SMA64);
    cudaFuncSetAttribute(k_gemm_xs,     cudaFuncAttributeMaxDynamicSharedMemorySize, SMA128);
    cudaFuncSetAttribute(k_gemm_scores, cudaFuncAttributeMaxDynamicSharedMemorySize, SMA128);
    cudaFuncSetAttribute(k_gemm_out,    cudaFuncAttributeMaxDynamicSharedMemorySize, SMA64);

    k_prep_u<<<(2 * D_ * D_) / 256, 256>>>(U, S1, S2);
    k_transpose_y<<<dim3(D_ / 32, N_ / 32, B_), dim3(32, 8)>>>(y);
    k_pos<<<N_, 256>>>(coords, pos_emb, p_temp);

    k_gemm_t<<<dim3(D_ / 64, (B_ * N_) / 128), 256, SMA64>>>(x, U);
    k_gemm_xs<<<dim3((2 * D_) / 128, (B_ * N_) / 128), 256, SMA128>>>();
    k_gemm_scores<<<dim3(N_ / 128, N_ / 128, B_ * 2), 256, SMA128>>>(y);

    k_mix<<<B_ * N_, 256>>>(gating, h_temp, heat);

    k_gemm_out<<<dim3(D_ / 64, N_ / 128, B_), 256, SMA64>>>(out);
}

// round 7
// speedup vs baseline: 1.3090x; 1.1438x over previous
#include <cuda_runtime.h>
#include <math.h>
#include <stdint.h>

constexpr int B_ = 8;
constexpr int N_ = 1024;
constexpr int D_ = 256;

// ---------------- scratch ----------------
__device__ float g_t[(size_t)B_ * N_ * D_];
__device__ float g_xs[(size_t)B_ * N_ * 2 * D_];
__device__ float g_U12T[2 * D_ * D_];
__device__ float g_pos[(size_t)N_ * N_];
__device__ float g_scores[(size_t)B_ * 2 * N_ * N_];
__device__ float g_attn[(size_t)B_ * N_ * N_];
__device__ float g_yT[(size_t)B_ * D_ * N_];

// ---------------- helpers ----------------
__device__ __forceinline__ uint32_t smaddr(const void* p) {
    return (uint32_t)__cvta_generic_to_shared(p);
}
__device__ __forceinline__ void ldm_x4(uint32_t* r, uint32_t addr) {
    asm volatile("ldmatrix.sync.aligned.m8n8.x4.shared.b16 {%0,%1,%2,%3}, [%4];"
                 : "=r"(r[0]), "=r"(r[1]), "=r"(r[2]), "=r"(r[3]) : "r"(addr));
}
__device__ __forceinline__ void mma_tf32(float* c, const uint32_t* a, const uint32_t* b) {
    asm volatile("mma.sync.aligned.m16n8k8.row.col.f32.tf32.tf32.f32 "
                 "{%0,%1,%2,%3}, {%4,%5,%6,%7}, {%8,%9}, {%0,%1,%2,%3};"
                 : "+f"(c[0]), "+f"(c[1]), "+f"(c[2]), "+f"(c[3])
                 : "r"(a[0]), "r"(a[1]), "r"(a[2]), "r"(a[3]), "r"(b[0]), "r"(b[1]));
}
// mask-based split: hi = v & 0xffffe000 (exact tf32-representable), lo = v - hi.
// HW truncates operand regs to tf32, so lo can be fed unmasked.
__device__ __forceinline__ void split4(const uint32_t* raw, uint32_t* h, uint32_t* l) {
    #pragma unroll
    for (int i = 0; i < 4; i++) {
        h[i] = raw[i] & 0xffffe000u;
        l[i] = __float_as_uint(__uint_as_float(raw[i]) - __uint_as_float(h[i]));
    }
}
__device__ __forceinline__ void cpa16(uint32_t dst, const float* src) {
    asm volatile("cp.async.cg.shared.global [%0], [%1], 16;" :: "r"(dst), "l"(src));
}
__device__ __forceinline__ void cp_commit() {
    asm volatile("cp.async.commit_group;" ::: "memory");
}
template <int n>
__device__ __forceinline__ void cp_wait() {
    asm volatile("cp.async.wait_group %0;" :: "n"(n) : "memory");
}

__device__ __forceinline__ float blk_max(float v, volatile float* sm) {
    #pragma unroll
    for (int o = 16; o > 0; o >>= 1) v = fmaxf(v, __shfl_xor_sync(0xffffffffu, v, o));
    if ((threadIdx.x & 31) == 0) sm[threadIdx.x >> 5] = v;
    __syncthreads();
    float r = sm[0];
    #pragma unroll
    for (int i = 1; i < 8; i++) r = fmaxf(r, sm[i]);
    __syncthreads();
    return r;
}
__device__ __forceinline__ float blk_sum(float v, volatile float* sm) {
    #pragma unroll
    for (int o = 16; o > 0; o >>= 1) v += __shfl_xor_sync(0xffffffffu, v, o);
    if ((threadIdx.x & 31) == 0) sm[threadIdx.x >> 5] = v;
    __syncthreads();
    float r = sm[0];
    #pragma unroll
    for (int i = 1; i < 8; i++) r += sm[i];
    __syncthreads();
    return r;
}

// ---------------- NT GEMM, raw-fp32 smem + mask-split 3xTF32 -----------------
// C[m,n] = alpha * sum_k A[m,k]*Bm[n,k]. Block 128xBN, BK=16, 256 threads,
// NS-stage cp.async pipeline, XOR-swizzled 64B-row smem tiles.
template <int BN, int NS>
__device__ __forceinline__ void gemm_rs(
    const float* __restrict__ A, int lda,
    const float* __restrict__ Bm, int ldb,
    float* __restrict__ C, int ldc,
    int K, float alpha)
{
    constexpr int BM = 128, BK = 16;
    constexpr int AST = BM * 64;   // bytes per A stage (row = 16 floats = 64B)
    constexpr int BST = BN * 64;
    constexpr int STG = AST + BST;
    constexpr int WN = BN / 2, nP = BN / 32;

    extern __shared__ float smem[];
    const uint32_t sbase = smaddr(smem);

    const int tid = threadIdx.x, lane = tid & 31, warp = tid >> 5;
    const int wm = (warp & 3) * 32, wn = (warp >> 2) * WN;
    const int m0 = blockIdx.y * BM, n0 = blockIdx.x * BN;

    // ---- cp.async producer mapping (16B chunks, 4 chunks per 64B row) ----
    const int ar = tid >> 1;
    const int ac0 = (tid & 1) * 2;
    const float* aSrc = A + (size_t)(m0 + ar) * lda + ac0 * 4;
    const int asw_st = (ar >> 1) & 3;
    const uint32_t aD0 = sbase + ar * 64 + ((ac0 ^ asw_st) * 16);
    const uint32_t aD1 = sbase + ar * 64 + (((ac0 + 1) ^ asw_st) * 16);

    const int br = (BN == 128) ? (tid >> 1) : (tid >> 2);
    const int bc0 = (BN == 128) ? ((tid & 1) * 2) : (tid & 3);
    const float* bSrc = Bm + (size_t)(n0 + br) * ldb + bc0 * 4;
    const int bsw_st = (br >> 1) & 3;
    const uint32_t bD0 = sbase + AST + br * 64 + ((bc0 ^ bsw_st) * 16);
    const uint32_t bD1 = sbase + AST + br * 64 + (((bc0 + 1) ^ bsw_st) * 16);

    auto issue = [&](int kt, int slot) {
        const uint32_t so = (uint32_t)slot * STG;
        const int ko = kt * BK;
        cpa16(aD0 + so, aSrc + ko);
        cpa16(aD1 + so, aSrc + ko + 4);
        cpa16(bD0 + so, bSrc + ko);
        if (BN == 128) cpa16(bD1 + so, bSrc + ko + 4);
    };

    // ---- ldmatrix consumer addressing ----
    const int mat = lane >> 3, idx = lane & 7;
    const int arow = wm + (mat & 1) * 8 + idx;
    const int asw = (arow >> 1) & 3;
    const int ach = mat >> 1;
    const uint32_t aK0 = (uint32_t)((ach ^ asw) * 16);
    const uint32_t aK1 = (uint32_t)(((ach + 2) ^ asw) * 16);
    const uint32_t aBase = sbase + arow * 64;

    const int brow = wn + (mat >> 1) * 8 + idx;
    const int bsw = (brow >> 1) & 3;
    const int bch = mat & 1;
    const uint32_t bK0 = (uint32_t)((bch ^ bsw) * 16);
    const uint32_t bK1 = (uint32_t)(((bch + 2) ^ bsw) * 16);
    const uint32_t bBase = sbase + AST + brow * 64;

    float acc[2][2 * nP][4] = {};

    const int ktiles = K / BK;
    #pragma unroll
    for (int s = 0; s < NS - 1; s++) { issue(s, s); cp_commit(); }

    for (int kt = 0; kt < ktiles; kt++) {
        cp_wait<NS - 2>();
        __syncthreads();
        const uint32_t so = (uint32_t)(kt % NS) * STG;

        if (kt + NS - 1 < ktiles) issue(kt + NS - 1, (kt + NS - 1) % NS);
        cp_commit();

        #pragma unroll
        for (int k8 = 0; k8 < 2; k8++) {
            const uint32_t akk = k8 ? aK1 : aK0;
            const uint32_t bkk = k8 ? bK1 : bK0;
            uint32_t ar0[4], ar1[4];
            ldm_x4(ar0, aBase + so + akk);
            ldm_x4(ar1, aBase + so + akk + 16 * 64);
            uint32_t ah[2][4], al[2][4];
            split4(ar0, ah[0], al[0]);
            split4(ar1, ah[1], al[1]);
            #pragma unroll
            for (int p = 0; p < nP; p++) {
                uint32_t braw[4], bh[4], bl[4];
                ldm_x4(braw, bBase + so + bkk + p * 16 * 64);
                split4(braw, bh, bl);
                #pragma unroll
                for (int f = 0; f < 2; f++) {
                    mma_tf32(acc[f][2 * p],     ah[f], bh);
                    mma_tf32(acc[f][2 * p + 1], ah[f], bh + 2);
                    mma_tf32(acc[f][2 * p],     ah[f], bl);
                    mma_tf32(acc[f][2 * p + 1], ah[f], bl + 2);
                    mma_tf32(acc[f][2 * p],     al[f], bh);
                    mma_tf32(acc[f][2 * p + 1], al[f], bh + 2);
                }
            }
        }
    }

    // ---- epilogue ----
    const int g = lane >> 2, tig = lane & 3;
    #pragma unroll
    for (int f = 0; f < 2; f++) {
        #pragma unroll
        for (int q = 0; q < 2 * nP; q++) {
            const int r = m0 + wm + f * 16 + g;
            const int c = n0 + wn + q * 8 + tig * 2;
            float2 v0 = {alpha * acc[f][q][0], alpha * acc[f][q][1]};
            float2 v1 = {alpha * acc[f][q][2], alpha * acc[f][q][3]};
            *(float2*)(C + (size_t)r * ldc + c) = v0;
            *(float2*)(C + (size_t)(r + 8) * ldc + c) = v1;
        }
    }
}

// smem bytes
constexpr int SMA128 = 4 * (128 + 128) * 64;  // 65536 (NS=4)
constexpr int SMA64  = 3 * (128 + 64) * 64;   // 36864 (NS=3)

// ---------------- GEMM wrappers ----------------
__global__ void __launch_bounds__(256, 3)
k_gemm_t(const float* __restrict__ x, const float* __restrict__ U) {
    gemm_rs<64, 3>(x, D_, U, D_, g_t, D_, D_, 1.0f);
}
__global__ void __launch_bounds__(256, 2)
k_gemm_xs() {
    gemm_rs<128, 4>(g_t, D_, g_U12T, D_, g_xs, 2 * D_, D_, 1.0f);
}
__global__ void __launch_bounds__(256, 2)
k_gemm_scores(const float* __restrict__ y) {
    int z = blockIdx.z;
    int b = z >> 1, k = z & 1;
    gemm_rs<128, 4>(g_xs + (size_t)b * N_ * (2 * D_) + k * D_, 2 * D_,
                    y + (size_t)b * N_ * D_, D_,
                    g_scores + (size_t)z * N_ * N_, N_,
                    D_, 0.0625f);
}
__global__ void __launch_bounds__(256, 3)
k_gemm_out(float* __restrict__ out) {
    int b = blockIdx.z;
    gemm_rs<64, 3>(g_attn + (size_t)b * N_ * N_, N_,
                   g_yT + (size_t)b * D_ * N_, N_,
                   out + (size_t)b * N_ * D_, D_,
                   N_, 1.0f);
}

// ---------------- prep kernels ----------------
__global__ void k_prep_u(const float* __restrict__ U,
                         const float* __restrict__ S1,
                         const float* __restrict__ S2) {
    int idxx = blockIdx.x * blockDim.x + threadIdx.x;
    int r = idxx >> 8;
    int d = idxx & 255;
    int k = r >> 8;
    int j = r & 255;
    float s = fabsf(k ? S2[d] : S1[d]);
    g_U12T[idxx] = s * U[d * 256 + j];
}

__global__ void k_transpose_y(const float* __restrict__ y) {
    __shared__ float tile[32][33];
    int b = blockIdx.z;
    int m0 = blockIdx.y * 32, j0 = blockIdx.x * 32;
    int tx = threadIdx.x, ty = threadIdx.y;
    #pragma unroll
    for (int i = ty; i < 32; i += 8)
        tile[i][tx] = y[((size_t)b * N_ + m0 + i) * D_ + j0 + tx];
    __syncthreads();
    #pragma unroll
    for (int i = ty; i < 32; i += 8)
        g_yT[((size_t)b * D_ + j0 + i) * N_ + m0 + tx] = tile[tx][i];
}

__global__ void k_pos(const float* __restrict__ coords,
                      const float* __restrict__ pos_emb,
                      const float* __restrict__ p_temp) {
    __shared__ float pe[6];
    __shared__ float sm[8];
    int n = blockIdx.x;
    int t = threadIdx.x;
    if (t < 6) pe[t] = pos_emb[n * 6 + t];
    __syncthreads();
    float pt = -fabsf(p_temp[0]);
    float lg[4];
    float lmax = -1e30f;
    #pragma unroll
    for (int i = 0; i < 4; i++) {
        int m = i * 256 + t;
        const float* c = coords + ((size_t)n * N_ + m) * 6;
        float a = c[0] * pe[0] + c[1] * pe[1] + c[2] * pe[2]
                + c[3] * pe[3] + c[4] * pe[4] + c[5] * pe[5];
        lg[i] = pt * a;
        lmax = fmaxf(lmax, lg[i]);
    }
    float mx = blk_max(lmax, sm);
    float lsum = 0.f;
    #pragma unroll
    for (int i = 0; i < 4; i++) { lg[i] = __expf(lg[i] - mx); lsum += lg[i]; }
    float s = blk_sum(lsum, sm);
    float inv = 1.0f / s;
    #pragma unroll
    for (int i = 0; i < 4; i++)
        g_pos[(size_t)n * N_ + i * 256 + t] = lg[i] * inv;
}

__global__ void k_mix(const float* __restrict__ gating,
                      const float* __restrict__ h_temp,
                      float* __restrict__ heat) {
    __shared__ float sm[8];
    int bn = blockIdx.x;
    int b = bn >> 10;
    int n = bn & (N_ - 1);
    int t = threadIdx.x;

    size_t base0 = ((size_t)(b * 2 + 0) * N_ + n) * N_;
    size_t base1 = ((size_t)(b * 2 + 1) * N_ + n) * N_;

    float s0[4], s1[4], pp[4];
    float lm0 = -1e30f, lm1 = -1e30f;
    #pragma unroll
    for (int i = 0; i < 4; i++) {
        int m = i * 256 + t;
        s0[i] = g_scores[base0 + m];
        s1[i] = g_scores[base1 + m];
        pp[i] = g_pos[(size_t)n * N_ + m];
        lm0 = fmaxf(lm0, s0[i]);
        lm1 = fmaxf(lm1, s1[i]);
    }
    float mx0 = blk_max(lm0, sm);
    float mx1 = blk_max(lm1, sm);

    float ls0 = 0.f, ls1 = 0.f;
    #pragma unroll
    for (int i = 0; i < 4; i++) {
        s0[i] = __expf(s0[i] - mx0); ls0 += s0[i];
        s1[i] = __expf(s1[i] - mx1); ls1 += s1[i];
    }
    float sum0 = blk_sum(ls0, sm);
    float sum1 = blk_sum(ls1, sm);
    float inv0 = 1.0f / sum0, inv1 = 1.0f / sum1;

    float g = 1.0f / (1.0f + __expf(-gating[0]));
    float og = 1.0f - g;

    float p0[4], p1[4];
    float le0 = 0.f, le1 = 0.f;
    #pragma unroll
    for (int i = 0; i < 4; i++) {
        p0[i] = og * s0[i] * inv0 + g * pp[i];
        p1[i] = og * s1[i] * inv1 + g * pp[i];
        le0 -= p0[i] * __logf(p0[i] + 1e-8f);
        le1 -= p1[i] * __logf(p1[i] + 1e-8f);
    }
    float ent0 = blk_sum(le0, sm);
    float ent1 = blk_sum(le1, sm);

    float ht = h_temp[0];
    float hm0 = 2.0f - 2.0f / (1.0f + __expf(-ht * ent0));
    float hm1 = 2.0f - 2.0f / (1.0f + __expf(-ht * ent1));
    int sel = (hm0 >= hm1) ? 0 : 1;

    #pragma unroll
    for (int i = 0; i < 4; i++)
        g_attn[(size_t)bn * N_ + i * 256 + t] = sel ? p1[i] : p0[i];

    if (t == 0) heat[bn] = sel ? hm1 : hm0;
}

// ---------------- launch ----------------
extern "C" void kernel_launch(void* const* d_in, const int* in_sizes, int n_in,
                              void* d_out, int out_size) {
    const float* x       = (const float*)d_in[0];
    const float* y       = (const float*)d_in[1];
    const float* coords  = (const float*)d_in[2];
    const float* U       = (const float*)d_in[3];
    const float* S1      = (const float*)d_in[4];
    const float* S2      = (const float*)d_in[5];
    const float* gating  = (const float*)d_in[6];
    const float* h_temp  = (const float*)d_in[7];
    const float* p_temp  = (const float*)d_in[8];
    const float* pos_emb = (const float*)d_in[9];

    float* out  = (float*)d_out;
    float* heat = out + (size_t)B_ * N_ * D_;

    cudaFuncSetAttribute(k_gemm_t,      cudaFuncAttributeMaxDynamicSharedMemorySize, SMA64);
    cudaFuncSetAttribute(k_gemm_xs,     cudaFuncAttributeMaxDynamicSharedMemorySize, SMA128);
    cudaFuncSetAttribute(k_gemm_scores, cudaFuncAttributeMaxDynamicSharedMemorySize, SMA128);
    cudaFuncSetAttribute(k_gemm_out,    cudaFuncAttributeMaxDynamicSharedMemorySize, SMA64);

    k_prep_u<<<(2 * D_ * D_) / 256, 256>>>(U, S1, S2);
    k_transpose_y<<<dim3(D_ / 32, N_ / 32, B_), dim3(32, 8)>>>(y);
    k_pos<<<N_, 256>>>(coords, pos_emb, p_temp);

    k_gemm_t<<<dim3(D_ / 64, (B_ * N_) / 128), 256, SMA64>>>(x, U);
    k_gemm_xs<<<dim3((2 * D_) / 128, (B_ * N_) / 128), 256, SMA128>>>();
    k_gemm_scores<<<dim3(N_ / 128, N_ / 128, B_ * 2), 256, SMA128>>>(y);

    k_mix<<<B_ * N_, 256>>>(gating, h_temp, heat);

    k_gemm_out<<<dim3(D_ / 64, N_ / 128, B_), 256, SMA64>>>(out);
}